// round 7
// baseline (speedup 1.0000x reference)
#include <cuda_runtime.h>

// Problem constants (fixed shapes per reference setup_inputs)
#define SS 512
#define DD 2640
#define MM 64
// Only batch 7 contributes. Final scale = 1/(S*(S-1)) / M / (B*100)
// mask_list is int32 on device (JAX x64 disabled downcasts jnp.int64).
//
// Norm expansion: sq_dist(m,s) = ||r_m||^2 + ||i_s||^2 - 2*(r_m . i_s).
// kA computes dot-product partials (the only O(M*S*D) term) + norm partials.

// Kernel A tiling: grid (4 s-tiles, 66 d-splits) = 264 CTAs, 256 threads.
// Tile: 64 m x 128 s x 40 d per CTA, single staged chunk. 2 CTAs/SM.
#define ND    66      // d splits
#define DPC   40      // d per CTA
#define CHQ   10      // float4 (d-quads) per row
#define ROWS  192     // 64 target rows + 128 input rows
#define R4    193     // padded row stride in float4 units (odd -> conflict-light)
#define STILE 128     // s per CTA
#define NELEM (ROWS * CHQ)   // 1920 staging float4s

#define NB    256     // kB CTA count (64 m x 4 s-chunks)

__device__ float g_part[ND * MM * SS];   // dot partials: 66*64*512*4B = 8.65 MB
__device__ float g_ni[ND * SS];          // input-row norm partials
__device__ float g_nr[ND * MM];          // target-row norm partials
__device__ float g_pred[NB];
__device__ int   g_ticket = 0;

// ---------------------------------------------------------------------------
// Kernel A: dot-product partials, f32x2-packed. smem trp[q][row] = float4 of
// 4 consecutive d. Rows 0..63 = gathered target rows, 64..191 = -input rows
// (negated so acc accumulates -r.i; kB applies sq = nr + ni + 2*acc).
// Thread (lane 0..31, wid 0..7) owns m = 8*wid..8*wid+7, s = lane+{0,32,64,96}.
// ---------------------------------------------------------------------------
__global__ __launch_bounds__(256, 2) void kA(const float* __restrict__ input,
                                             const int* __restrict__ mask,
                                             const float* __restrict__ target)
{
    __shared__ __align__(16) float4 trp[CHQ * R4];   // 10*193*16 = 30880 B
    __shared__ const float* rowptr[ROWS];

    const int tid  = threadIdx.x;
    const int lane = tid & 31;
    const int wid  = tid >> 5;
    const int sbase = blockIdx.x * STILE;
    const int dbase = blockIdx.y * DPC;

    if (tid < MM) {
        int im = mask[7 * MM + tid];
        rowptr[tid] = target + ((size_t)7 * SS + (size_t)im) * DD + dbase;
    } else if (tid < ROWS) {
        rowptr[tid] = input + ((size_t)7 * SS + (size_t)(sbase + tid - MM)) * DD + dbase;
    }
    __syncthreads();

    // ---- stage global -> transposed smem (8 independent LDG.128 in flight) ----
    #pragma unroll
    for (int k = 0; k < 8; ++k) {
        int i = tid + k * 256;
        if (i < NELEM) {
            int row = i / CHQ, c = i - row * CHQ;
            float4 v = *(reinterpret_cast<const float4*>(rowptr[row]) + c);
            if (row >= MM) { v.x = -v.x; v.y = -v.y; v.z = -v.z; v.w = -v.w; }
            trp[c * R4 + row] = v;
        }
    }
    __syncthreads();

    // ---- norm partials from staged tile (negation is square-invariant) ----
    if (tid < ROWS) {
        float ns = 0.0f;
        #pragma unroll
        for (int c = 0; c < CHQ; ++c) {
            float4 v = trp[c * R4 + tid];
            ns += v.x * v.x + v.y * v.y + v.z * v.z + v.w * v.w;
        }
        if (tid < MM) {
            if (blockIdx.x == 0) g_nr[blockIdx.y * MM + tid] = ns;
        } else {
            g_ni[blockIdx.y * SS + sbase + (tid - MM)] = ns;
        }
    }

    // ---- compute: 10 d-quad iterations, 64 packed FMAs + 12 LDS each ----
    unsigned long long acc[32];
    #pragma unroll
    for (int i = 0; i < 32; ++i) acc[i] = 0ull;   // float2(0,0)

    #pragma unroll 2
    for (int q = 0; q < CHQ; ++q) {
        const float4* base = trp + q * R4;
        ulonglong2 iv[4];
        #pragma unroll
        for (int b = 0; b < 4; ++b)   // s rows: lane-contiguous LDS.128
            iv[b] = *reinterpret_cast<const ulonglong2*>(base + MM + lane + 32 * b);
        #pragma unroll
        for (int a = 0; a < 8; ++a) { // m rows: warp-broadcast LDS.128
            ulonglong2 rv = *reinterpret_cast<const ulonglong2*>(base + 8 * wid + a);
            #pragma unroll
            for (int b = 0; b < 4; ++b) {
                asm("fma.rn.f32x2 %0, %1, %2, %0;"
                    : "+l"(acc[a * 4 + b]) : "l"(rv.x), "l"(iv[b].x));
                asm("fma.rn.f32x2 %0, %1, %2, %0;"
                    : "+l"(acc[a * 4 + b]) : "l"(rv.y), "l"(iv[b].y));
            }
        }
    }

    // ---- epilogue: fold packed halves, write dot partials (coalesced) ----
    // acc holds sum of r*(-i) = -dot.
    float* outp = g_part + (size_t)blockIdx.y * (MM * SS) + sbase;
    #pragma unroll
    for (int a = 0; a < 8; ++a) {
        int m = 8 * wid + a;
        #pragma unroll
        for (int b = 0; b < 4; ++b) {
            unsigned long long v = acc[a * 4 + b];
            float lo = __uint_as_float((unsigned)(v & 0xffffffffu));
            float hi = __uint_as_float((unsigned)(v >> 32));
            outp[(size_t)m * SS + lane + 32 * b] = lo + hi;   // = -dot partial
        }
    }
}

// ---------------------------------------------------------------------------
// Kernel B: recombine norms + dot, hinge, reduce. Grid: 256 CTAs
// (blockIdx = chunk*64 + m), 128 threads, one s per thread, unrolled z-loop
// with 6 accumulators for high MLP. Last block (atomic ticket) does the final
// fixed-order sum (deterministic).
// ---------------------------------------------------------------------------
__global__ __launch_bounds__(128) void kB(const int* __restrict__ mask,
                                          float* __restrict__ out)
{
    const int m     = blockIdx.x & 63;
    const int chunk = blockIdx.x >> 6;
    const int tid   = threadIdx.x;
    const int s     = chunk * 128 + tid;
    const int im    = mask[7 * MM + m];

    // -dot over z: 66 independent coalesced loads, 6 accumulators
    const float* p = g_part + (size_t)m * SS + s;
    float a0 = 0, a1 = 0, a2 = 0, a3 = 0, a4 = 0, a5 = 0;
    #pragma unroll
    for (int z = 0; z < ND; z += 6) {
        a0 += p[(size_t)(z + 0) * (MM * SS)];
        a1 += p[(size_t)(z + 1) * (MM * SS)];
        a2 += p[(size_t)(z + 2) * (MM * SS)];
        a3 += p[(size_t)(z + 3) * (MM * SS)];
        a4 += p[(size_t)(z + 4) * (MM * SS)];
        a5 += p[(size_t)(z + 5) * (MM * SS)];
    }
    float ndot = ((a0 + a1) + (a2 + a3)) + (a4 + a5);

    // input-row norm for this s (coalesced over lanes)
    float b0 = 0, b1 = 0, b2 = 0, b3 = 0, b4 = 0, b5 = 0;
    #pragma unroll
    for (int z = 0; z < ND; z += 6) {
        b0 += g_ni[(z + 0) * SS + s];
        b1 += g_ni[(z + 1) * SS + s];
        b2 += g_ni[(z + 2) * SS + s];
        b3 += g_ni[(z + 3) * SS + s];
        b4 += g_ni[(z + 4) * SS + s];
        b5 += g_ni[(z + 5) * SS + s];
    }
    float ni = ((b0 + b1) + (b2 + b3)) + (b4 + b5);

    // target-row norm for m: warp-uniform broadcast loads
    float c0 = 0, c1 = 0, c2 = 0, c3 = 0, c4 = 0, c5 = 0;
    #pragma unroll
    for (int z = 0; z < ND; z += 6) {
        c0 += g_nr[(z + 0) * MM + m];
        c1 += g_nr[(z + 1) * MM + m];
        c2 += g_nr[(z + 2) * MM + m];
        c3 += g_nr[(z + 3) * MM + m];
        c4 += g_nr[(z + 4) * MM + m];
        c5 += g_nr[(z + 5) * MM + m];
    }
    float nr = ((c0 + c1) + (c2 + c3)) + (c4 + c5);

    float sq = nr + ni + 2.0f * ndot;
    int d = im - s;
    if (d < 0) d = -d;
    float val = (d <= 1) ? sq : fmaxf(0.0f, 15000.0f - sq);

    // block reduce (128 threads)
    __shared__ float red[4];
    #pragma unroll
    for (int o = 16; o >= 1; o >>= 1)
        val += __shfl_down_sync(0xffffffffu, val, o);
    if ((tid & 31) == 0) red[tid >> 5] = val;
    __syncthreads();
    if (tid == 0) {
        g_pred[blockIdx.x] = (red[0] + red[1]) + (red[2] + red[3]);
    }

    // last-block final reduce (deterministic fixed-order sum)
    __shared__ int is_last;
    __threadfence();
    if (tid == 0) is_last = (atomicAdd(&g_ticket, 1) == NB - 1);
    __syncthreads();
    if (is_last && tid == 0) {
        __threadfence();
        float tot = 0.0f;
        #pragma unroll
        for (int i = 0; i < NB; ++i) tot += g_pred[i];
        const float scale = (float)(1.0 / (261632.0 * 64.0 * 800.0)); // 1/(S(S-1))/M/(B*100)
        out[0] = tot * scale;
        g_ticket = 0;   // reset for next graph replay
    }
}

// ---------------------------------------------------------------------------
extern "C" void kernel_launch(void* const* d_in, const int* in_sizes, int n_in,
                              void* d_out, int out_size)
{
    const float* input  = (const float*)d_in[0];
    const int*   mask   = (const int*)d_in[1];
    const float* target = (const float*)d_in[2];
    float*       out    = (float*)d_out;

    kA<<<dim3(4, ND), 256>>>(input, mask, target);
    kB<<<NB, 128>>>(mask, out);
}

// round 9
// speedup vs baseline: 1.0519x; 1.0519x over previous
#include <cuda_runtime.h>

// Problem constants (fixed shapes per reference setup_inputs)
#define SS 512
#define DD 2640
#define MM 64
// Only batch 7 contributes. Final scale = 1/(S*(S-1)) / M / (B*100)
// mask_list is int32 on device (JAX x64 disabled downcasts jnp.int64).
//
// Norm expansion with folded norms:
//   sq(m,s) = ||r_m||^2 + ||i_s||^2 - 2*(r_m . i_s)
//   g_part[z][m][s] = -(r.i)_z + 0.5*||r_m||^2_z + 0.5*||i_s||^2_z
//   => sq(m,s) = 2 * sum_z g_part[z][m][s]      (kB reads ONE stream only)

// Kernel A tiling: grid (4 s-tiles, 66 d-splits) = 264 CTAs, 256 threads.
// Tile: 64 m x 128 s x 40 d per CTA, single staged chunk. 2 CTAs/SM.
#define ND    66      // d splits
#define DPC   40      // d per CTA
#define CHQ   10      // float4 (d-quads) per row
#define ROWS  192     // 64 target rows + 128 input rows
#define R4    193     // padded row stride in float4 units (odd -> conflict-light)
#define STILE 128     // s per CTA
#define NELEM (ROWS * CHQ)   // 1920 staging float4s

__device__ float g_part[ND * MM * SS];   // folded partials: 8.65 MB
__device__ float g_pred[MM];
__device__ int   g_ticket = 0;

// ---------------------------------------------------------------------------
// Kernel A: folded partials, f32x2-packed. smem trp[q][row] = float4 of
// 4 consecutive d. Rows 0..63 = gathered target rows, 64..191 = -input rows
// (negated so acc accumulates -r.i; squares unaffected).
// Thread (lane 0..31, wid 0..7) owns m = 8*wid..8*wid+7, s = lane+{0,32,64,96}.
// ---------------------------------------------------------------------------
__global__ __launch_bounds__(256, 2) void kA(const float* __restrict__ input,
                                             const int* __restrict__ mask,
                                             const float* __restrict__ target)
{
    __shared__ __align__(16) float4 trp[CHQ * R4];   // 10*193*16 = 30880 B
    __shared__ const float* rowptr[ROWS];
    __shared__ float hn_r[MM];     // 0.5 * ||r_m||^2 partial (this z)
    __shared__ float hn_i[STILE];  // 0.5 * ||i_s||^2 partial (this z)

    const int tid  = threadIdx.x;
    const int lane = tid & 31;
    const int wid  = tid >> 5;
    const int sbase = blockIdx.x * STILE;
    const int dbase = blockIdx.y * DPC;

    if (tid < MM) {
        int im = mask[7 * MM + tid];
        rowptr[tid] = target + ((size_t)7 * SS + (size_t)im) * DD + dbase;
    } else if (tid < ROWS) {
        rowptr[tid] = input + ((size_t)7 * SS + (size_t)(sbase + tid - MM)) * DD + dbase;
    }
    __syncthreads();

    // ---- stage global -> transposed smem (8 independent LDG.128 in flight) ----
    #pragma unroll
    for (int k = 0; k < 8; ++k) {
        int i = tid + k * 256;
        if (i < NELEM) {
            int row = i / CHQ, c = i - row * CHQ;
            float4 v = *(reinterpret_cast<const float4*>(rowptr[row]) + c);
            if (row >= MM) { v.x = -v.x; v.y = -v.y; v.z = -v.z; v.w = -v.w; }
            trp[c * R4 + row] = v;
        }
    }
    __syncthreads();

    // ---- half-norm partials from staged tile (negation square-invariant) ----
    if (tid < ROWS) {
        float ns = 0.0f;
        #pragma unroll
        for (int c = 0; c < CHQ; ++c) {
            float4 v = trp[c * R4 + tid];
            ns += v.x * v.x + v.y * v.y + v.z * v.z + v.w * v.w;
        }
        if (tid < MM) hn_r[tid] = 0.5f * ns;
        else          hn_i[tid - MM] = 0.5f * ns;
    }

    // ---- compute: 10 d-quad iterations, 64 packed FMAs + 12 LDS each ----
    unsigned long long acc[32];
    #pragma unroll
    for (int i = 0; i < 32; ++i) acc[i] = 0ull;   // float2(0,0)

    #pragma unroll 2
    for (int q = 0; q < CHQ; ++q) {
        const float4* base = trp + q * R4;
        ulonglong2 iv[4];
        #pragma unroll
        for (int b = 0; b < 4; ++b)   // s rows: lane-contiguous LDS.128
            iv[b] = *reinterpret_cast<const ulonglong2*>(base + MM + lane + 32 * b);
        #pragma unroll
        for (int a = 0; a < 8; ++a) { // m rows: warp-broadcast LDS.128
            ulonglong2 rv = *reinterpret_cast<const ulonglong2*>(base + 8 * wid + a);
            #pragma unroll
            for (int b = 0; b < 4; ++b) {
                asm("fma.rn.f32x2 %0, %1, %2, %0;"
                    : "+l"(acc[a * 4 + b]) : "l"(rv.x), "l"(iv[b].x));
                asm("fma.rn.f32x2 %0, %1, %2, %0;"
                    : "+l"(acc[a * 4 + b]) : "l"(rv.y), "l"(iv[b].y));
            }
        }
    }
    __syncthreads();   // hn_r/hn_i writes (pre-compute) -> epilogue reads

    // ---- epilogue: fold halves + add half-norms, write folded partials ----
    float* outp = g_part + (size_t)blockIdx.y * (MM * SS) + sbase;
    #pragma unroll
    for (int a = 0; a < 8; ++a) {
        int m = 8 * wid + a;
        float hr = hn_r[m];
        #pragma unroll
        for (int b = 0; b < 4; ++b) {
            unsigned long long v = acc[a * 4 + b];
            float lo = __uint_as_float((unsigned)(v & 0xffffffffu));
            float hi = __uint_as_float((unsigned)(v >> 32));
            int sl = lane + 32 * b;
            outp[(size_t)m * SS + sl] = (lo + hi) + hr + hn_i[sl];
        }
    }
}

// ---------------------------------------------------------------------------
// Kernel B: sq = 2 * sum_z g_part[z][m][s], hinge, reduce.
// Grid: 64 CTAs (one per m), 128 threads, each owns 4 consecutive s (float4).
// 66 independent float4 loads into 8 accumulators -> high MLP.
// Last block (atomic ticket) does the final fixed-order sum (deterministic).
// ---------------------------------------------------------------------------
__global__ __launch_bounds__(128) void kB(const int* __restrict__ mask,
                                          float* __restrict__ out)
{
    const int m   = blockIdx.x;
    const int tid = threadIdx.x;
    const int s0  = tid * 4;
    const int im  = mask[7 * MM + m];

    const float4* p = reinterpret_cast<const float4*>(g_part) + (size_t)m * (SS / 4) + tid;
    const size_t zstride = (size_t)MM * SS / 4;

    float4 A[8];
    #pragma unroll
    for (int i = 0; i < 8; ++i) A[i] = make_float4(0.f, 0.f, 0.f, 0.f);

    #pragma unroll
    for (int z = 0; z < ND; ++z) {
        float4 v = p[z * zstride];
        float4& a = A[z & 7];
        a.x += v.x; a.y += v.y; a.z += v.z; a.w += v.w;
    }
    float4 t01 = make_float4(A[0].x + A[1].x, A[0].y + A[1].y, A[0].z + A[1].z, A[0].w + A[1].w);
    float4 t23 = make_float4(A[2].x + A[3].x, A[2].y + A[3].y, A[2].z + A[3].z, A[2].w + A[3].w);
    float4 t45 = make_float4(A[4].x + A[5].x, A[4].y + A[5].y, A[4].z + A[5].z, A[4].w + A[5].w);
    float4 t67 = make_float4(A[6].x + A[7].x, A[6].y + A[7].y, A[6].z + A[7].z, A[6].w + A[7].w);
    float4 sum = make_float4((t01.x + t23.x) + (t45.x + t67.x),
                             (t01.y + t23.y) + (t45.y + t67.y),
                             (t01.z + t23.z) + (t45.z + t67.z),
                             (t01.w + t23.w) + (t45.w + t67.w));

    float val = 0.0f;
    const float* sc = &sum.x;
    #pragma unroll
    for (int j = 0; j < 4; ++j) {
        float sq = 2.0f * sc[j];
        int d = im - (s0 + j);
        if (d < 0) d = -d;
        val += (d <= 1) ? sq : fmaxf(0.0f, 15000.0f - sq);
    }

    // block reduce (128 threads)
    __shared__ float red[4];
    #pragma unroll
    for (int o = 16; o >= 1; o >>= 1)
        val += __shfl_down_sync(0xffffffffu, val, o);
    if ((tid & 31) == 0) red[tid >> 5] = val;
    __syncthreads();
    if (tid == 0) g_pred[m] = (red[0] + red[1]) + (red[2] + red[3]);

    // last-block final reduce (deterministic fixed-order sum)
    __shared__ int is_last;
    __threadfence();
    if (tid == 0) is_last = (atomicAdd(&g_ticket, 1) == MM - 1);
    __syncthreads();
    if (is_last && tid == 0) {
        __threadfence();
        float tot = 0.0f;
        #pragma unroll
        for (int i = 0; i < MM; ++i) tot += g_pred[i];
        const float scale = (float)(1.0 / (261632.0 * 64.0 * 800.0)); // 1/(S(S-1))/M/(B*100)
        out[0] = tot * scale;
        g_ticket = 0;   // reset for next graph replay
    }
}

// ---------------------------------------------------------------------------
extern "C" void kernel_launch(void* const* d_in, const int* in_sizes, int n_in,
                              void* d_out, int out_size)
{
    const float* input  = (const float*)d_in[0];
    const int*   mask   = (const int*)d_in[1];
    const float* target = (const float*)d_in[2];
    float*       out    = (float*)d_out;

    kA<<<dim3(4, ND), 256>>>(input, mask, target);
    kB<<<MM, 128>>>(mask, out);
}

// round 10
// speedup vs baseline: 1.2150x; 1.1550x over previous
#include <cuda_runtime.h>

// Problem constants (fixed shapes per reference setup_inputs)
#define SS 512
#define DD 2640
#define MM 64
// Only batch 7 contributes. Final scale = 1/(S*(S-1)) / M / (B*100)
// mask_list is int32 on device (JAX x64 disabled downcasts jnp.int64).
//
// Norm expansion with folded norms:
//   g_part[z][m][s] = -(r.i)_z + 0.5*||r_m||^2_z + 0.5*||i_s||^2_z
//   => sq(m,s) = 2 * sum_z g_part[z][m][s]

// Kernel A tiling: grid (4 s-tiles, 66 d-splits) = 264 CTAs, 256 threads.
#define ND    66      // d splits
#define DPC   40      // d per CTA
#define CHQ   10      // float4 (d-quads) per row
#define ROWS  192     // 64 target rows + 128 input rows
#define R4    193     // padded row stride in float4 units
#define STILE 128     // s per CTA
#define NELEM (ROWS * CHQ)

#define NB    512     // kB CTAs: 64 m x 8 s-chunks

__device__ float g_part[ND * MM * SS];   // folded partials: 8.65 MB
__device__ float g_pred[NB];
__device__ int   g_ticket = 0;

// ---------------------------------------------------------------------------
// Kernel A: folded partials, f32x2-packed (unchanged from Round 7).
// ---------------------------------------------------------------------------
__global__ __launch_bounds__(256, 2) void kA(const float* __restrict__ input,
                                             const int* __restrict__ mask,
                                             const float* __restrict__ target)
{
    __shared__ __align__(16) float4 trp[CHQ * R4];   // 30880 B
    __shared__ const float* rowptr[ROWS];
    __shared__ float hn_r[MM];     // 0.5 * ||r_m||^2 partial (this z)
    __shared__ float hn_i[STILE];  // 0.5 * ||i_s||^2 partial (this z)

    const int tid  = threadIdx.x;
    const int lane = tid & 31;
    const int wid  = tid >> 5;
    const int sbase = blockIdx.x * STILE;
    const int dbase = blockIdx.y * DPC;

    if (tid < MM) {
        int im = mask[7 * MM + tid];
        rowptr[tid] = target + ((size_t)7 * SS + (size_t)im) * DD + dbase;
    } else if (tid < ROWS) {
        rowptr[tid] = input + ((size_t)7 * SS + (size_t)(sbase + tid - MM)) * DD + dbase;
    }
    __syncthreads();

    #pragma unroll
    for (int k = 0; k < 8; ++k) {
        int i = tid + k * 256;
        if (i < NELEM) {
            int row = i / CHQ, c = i - row * CHQ;
            float4 v = *(reinterpret_cast<const float4*>(rowptr[row]) + c);
            if (row >= MM) { v.x = -v.x; v.y = -v.y; v.z = -v.z; v.w = -v.w; }
            trp[c * R4 + row] = v;
        }
    }
    __syncthreads();

    if (tid < ROWS) {
        float ns = 0.0f;
        #pragma unroll
        for (int c = 0; c < CHQ; ++c) {
            float4 v = trp[c * R4 + tid];
            ns += v.x * v.x + v.y * v.y + v.z * v.z + v.w * v.w;
        }
        if (tid < MM) hn_r[tid] = 0.5f * ns;
        else          hn_i[tid - MM] = 0.5f * ns;
    }

    unsigned long long acc[32];
    #pragma unroll
    for (int i = 0; i < 32; ++i) acc[i] = 0ull;

    #pragma unroll 2
    for (int q = 0; q < CHQ; ++q) {
        const float4* base = trp + q * R4;
        ulonglong2 iv[4];
        #pragma unroll
        for (int b = 0; b < 4; ++b)
            iv[b] = *reinterpret_cast<const ulonglong2*>(base + MM + lane + 32 * b);
        #pragma unroll
        for (int a = 0; a < 8; ++a) {
            ulonglong2 rv = *reinterpret_cast<const ulonglong2*>(base + 8 * wid + a);
            #pragma unroll
            for (int b = 0; b < 4; ++b) {
                asm("fma.rn.f32x2 %0, %1, %2, %0;"
                    : "+l"(acc[a * 4 + b]) : "l"(rv.x), "l"(iv[b].x));
                asm("fma.rn.f32x2 %0, %1, %2, %0;"
                    : "+l"(acc[a * 4 + b]) : "l"(rv.y), "l"(iv[b].y));
            }
        }
    }
    __syncthreads();

    float* outp = g_part + (size_t)blockIdx.y * (MM * SS) + sbase;
    #pragma unroll
    for (int a = 0; a < 8; ++a) {
        int m = 8 * wid + a;
        float hr = hn_r[m];
        #pragma unroll
        for (int b = 0; b < 4; ++b) {
            unsigned long long v = acc[a * 4 + b];
            float lo = __uint_as_float((unsigned)(v & 0xffffffffu));
            float hi = __uint_as_float((unsigned)(v >> 32));
            int sl = lane + 32 * b;
            outp[(size_t)m * SS + sl] = (lo + hi) + hr + hn_i[sl];
        }
    }
}

// ---------------------------------------------------------------------------
// Kernel B: z-reduction SPLIT ACROSS LANES for MLP-by-parallelism.
// Grid: 512 CTAs = (m = blockIdx&63, schunk = blockIdx>>6 of 64 s).
// 128 threads: tid = s4*8 + zc. Lane-group of 8 (zc) splits the 66 z-planes:
// zc handles z = zc + 8k (k<8) plus z = zc+64 for zc<2. 8-9 independent
// unrolled LDG.128 per thread. shfl_xor folds the zc group; lane zc==0
// applies the hinge for its 4 s values. Deterministic ticket finish.
// ---------------------------------------------------------------------------
__global__ __launch_bounds__(128) void kB(const int* __restrict__ mask,
                                          float* __restrict__ out)
{
    const int m      = blockIdx.x & 63;
    const int schunk = blockIdx.x >> 6;      // 0..7
    const int tid    = threadIdx.x;
    const int s4     = tid >> 3;             // 0..15 (float4 group within chunk)
    const int zc     = tid & 7;              // 0..7  (z split)
    const int im     = mask[7 * MM + m];

    const size_t zs = (size_t)MM * SS / 4;   // z-stride in float4
    const float4* p = reinterpret_cast<const float4*>(g_part)
                    + (size_t)m * (SS / 4) + schunk * 16 + s4 + (size_t)zc * zs;

    float4 v[8];
    #pragma unroll
    for (int k = 0; k < 8; ++k) v[k] = p[(size_t)(8 * k) * zs];   // z = zc + 8k
    float4 v8 = make_float4(0.f, 0.f, 0.f, 0.f);
    if (zc < 2) v8 = p[(size_t)64 * zs];                           // z = zc + 64

    float4 t;
    t.x = (((v[0].x + v[1].x) + (v[2].x + v[3].x)) + ((v[4].x + v[5].x) + (v[6].x + v[7].x))) + v8.x;
    t.y = (((v[0].y + v[1].y) + (v[2].y + v[3].y)) + ((v[4].y + v[5].y) + (v[6].y + v[7].y))) + v8.y;
    t.z = (((v[0].z + v[1].z) + (v[2].z + v[3].z)) + ((v[4].z + v[5].z) + (v[6].z + v[7].z))) + v8.z;
    t.w = (((v[0].w + v[1].w) + (v[2].w + v[3].w)) + ((v[4].w + v[5].w) + (v[6].w + v[7].w))) + v8.w;

    // fold the 8-lane zc group (xor butterfly stays within the group)
    #pragma unroll
    for (int o = 4; o >= 1; o >>= 1) {
        t.x += __shfl_xor_sync(0xffffffffu, t.x, o);
        t.y += __shfl_xor_sync(0xffffffffu, t.y, o);
        t.z += __shfl_xor_sync(0xffffffffu, t.z, o);
        t.w += __shfl_xor_sync(0xffffffffu, t.w, o);
    }

    float val = 0.0f;
    if (zc == 0) {
        const int s0 = schunk * 64 + s4 * 4;
        const float* c = &t.x;
        #pragma unroll
        for (int j = 0; j < 4; ++j) {
            float sq = 2.0f * c[j];
            int d = im - (s0 + j);
            if (d < 0) d = -d;
            val += (d <= 1) ? sq : fmaxf(0.0f, 15000.0f - sq);
        }
    }

    // block reduce
    __shared__ float red[4];
    #pragma unroll
    for (int o = 16; o >= 1; o >>= 1)
        val += __shfl_down_sync(0xffffffffu, val, o);
    if ((tid & 31) == 0) red[tid >> 5] = val;
    __syncthreads();
    if (tid == 0) g_pred[blockIdx.x] = (red[0] + red[1]) + (red[2] + red[3]);

    // last-block final reduce (deterministic fixed-order partial sums)
    __shared__ int is_last;
    __threadfence();
    if (tid == 0) is_last = (atomicAdd(&g_ticket, 1) == NB - 1);
    __syncthreads();
    if (is_last) {
        __threadfence();
        float t2 = 0.0f;
        #pragma unroll
        for (int i = 0; i < NB / 128; ++i) t2 += g_pred[tid + i * 128];
        #pragma unroll
        for (int o = 16; o >= 1; o >>= 1)
            t2 += __shfl_down_sync(0xffffffffu, t2, o);
        if ((tid & 31) == 0) red[tid >> 5] = t2;
        __syncthreads();
        if (tid == 0) {
            const float scale = (float)(1.0 / (261632.0 * 64.0 * 800.0)); // 1/(S(S-1))/M/(B*100)
            out[0] = ((red[0] + red[1]) + (red[2] + red[3])) * scale;
            g_ticket = 0;   // reset for next graph replay
        }
    }
}

// ---------------------------------------------------------------------------
extern "C" void kernel_launch(void* const* d_in, const int* in_sizes, int n_in,
                              void* d_out, int out_size)
{
    const float* input  = (const float*)d_in[0];
    const int*   mask   = (const int*)d_in[1];
    const float* target = (const float*)d_in[2];
    float*       out    = (float*)d_out;

    kA<<<dim3(4, ND), 256>>>(input, mask, target);
    kB<<<NB, 128>>>(mask, out);
}